// round 1
// baseline (speedup 1.0000x reference)
#include <cuda_runtime.h>
#include <math.h>

#define B_SZ  16
#define L_SZ  1024
#define DM    166
#define DI    332
#define DS    16
#define DCV   4
#define DTR   11
#define NLAY  3
#define XZW   (2*DI)        // 664
#define DBCW  (DTR + 2*DS)  // 43
#define ROWS  (B_SZ*L_SZ)   // 16384
#define EPSV  1e-5f

// -------- scratch (device globals; no allocation allowed) --------
__device__ float g_hidden[ROWS*DM];
__device__ float g_resid [ROWS*DM];
__device__ float g_hnorm [ROWS*DM];
__device__ float g_xz    [ROWS*XZW];
__device__ float g_xc    [ROWS*DI];
__device__ float g_dbc   [ROWS*DBCW];
__device__ float g_dt    [ROWS*DI];
__device__ float g_y     [ROWS*DI];

// -------- embedding lookup --------
__global__ void k_embed(const int* __restrict__ fasta, const float* __restrict__ emb) {
    int idx = blockIdx.x * blockDim.x + threadIdx.x;
    if (idx >= ROWS*DM) return;
    int r = idx / DM, m = idx - r*DM;
    g_hidden[idx] = emb[fasta[r]*DM + m];
}

// -------- residual add + rmsnorm (warp per row) --------
__global__ void k_addnorm(const float* __restrict__ nw, int first) {
    int row  = blockIdx.x * 8 + (threadIdx.x >> 5);
    int lane = threadIdx.x & 31;
    const float* hp = g_hidden + row*DM;
    float* rp = g_resid + row*DM;
    float v[6]; float ss = 0.f;
#pragma unroll
    for (int j = 0; j < 6; j++) {
        int i = lane + 32*j;
        float x = 0.f;
        if (i < DM) {
            x = hp[i];
            if (!first) x += rp[i];
            rp[i] = x;
        }
        v[j] = x; ss += x*x;
    }
#pragma unroll
    for (int o = 16; o; o >>= 1) ss += __shfl_xor_sync(0xffffffffu, ss, o);
    float sc = rsqrtf(ss * (1.f/DM) + EPSV);
    float* op = g_hnorm + row*DM;
#pragma unroll
    for (int j = 0; j < 6; j++) {
        int i = lane + 32*j;
        if (i < DM) op[i] = v[j] * sc * nw[i];
    }
}

// -------- final residual add + rmsnorm -> v (writes d_out region) --------
__global__ void k_finalnorm(const float* __restrict__ nfw, float* __restrict__ vout) {
    int row  = blockIdx.x * 8 + (threadIdx.x >> 5);
    int lane = threadIdx.x & 31;
    const float* hp = g_hidden + row*DM;
    const float* rp = g_resid  + row*DM;
    float v[6]; float ss = 0.f;
#pragma unroll
    for (int j = 0; j < 6; j++) {
        int i = lane + 32*j;
        float x = 0.f;
        if (i < DM) x = hp[i] + rp[i];
        v[j] = x; ss += x*x;
    }
#pragma unroll
    for (int o = 16; o; o >>= 1) ss += __shfl_xor_sync(0xffffffffu, ss, o);
    float sc = rsqrtf(ss * (1.f/DM) + EPSV);
    float* op = vout + row*DM;
#pragma unroll
    for (int j = 0; j < 6; j++) {
        int i = lane + 32*j;
        if (i < DM) op[i] = v[j] * sc * nfw[i];
    }
}

// -------- max over L (warp per (b,m)) --------
__global__ void k_maxL(const float* __restrict__ v, float* __restrict__ ve) {
    int w    = blockIdx.x * 8 + (threadIdx.x >> 5);   // 0..2655  (332*8 = 2656 exactly)
    int lane = threadIdx.x & 31;
    int b = w / DM, m = w - b*DM;
    float mx = -INFINITY;
    for (int l = lane; l < L_SZ; l += 32)
        mx = fmaxf(mx, v[(b*L_SZ + l)*DM + m]);
#pragma unroll
    for (int o = 16; o; o >>= 1) mx = fmaxf(mx, __shfl_xor_sync(0xffffffffu, mx, o));
    if (lane == 0) ve[b*DM + m] = mx;
}

// -------- generic fp32 GEMM: C[M,N] = A[M,K] * W[N,K]^T --------
// block tile 128(M) x 64(N), 256 threads, 8x4 micro-tile, TK=16
#define GTM 128
#define GTN 64
#define GTK 16
__global__ void k_gemm(const float* __restrict__ A, const float* __restrict__ W,
                       float* __restrict__ C, int N, int K) {
    __shared__ float As[GTK][GTM];
    __shared__ float Ws[GTK][GTN];
    int tid = threadIdx.x;
    int m0 = blockIdx.y * GTM;
    int n0 = blockIdx.x * GTN;
    int tx = tid & 15, ty = tid >> 4;
    float acc[8][4];
#pragma unroll
    for (int i = 0; i < 8; i++)
#pragma unroll
        for (int j = 0; j < 4; j++) acc[i][j] = 0.f;

    for (int kk = 0; kk < K; kk += GTK) {
#pragma unroll
        for (int i = 0; i < 8; i++) {               // A tile: 2048 elems
            int idx = tid + i*256;
            int m = idx >> 4, k = idx & 15;
            float vv = 0.f;
            if (kk + k < K) vv = A[(m0 + m)*K + kk + k];
            As[k][m] = vv;
        }
#pragma unroll
        for (int i = 0; i < 4; i++) {               // W tile: 1024 elems
            int idx = tid + i*256;
            int n = idx >> 4, k = idx & 15;
            float vv = 0.f;
            if ((n0 + n) < N && (kk + k) < K) vv = W[(n0 + n)*K + kk + k];
            Ws[k][n] = vv;
        }
        __syncthreads();
#pragma unroll
        for (int k = 0; k < GTK; k++) {
            float a[8], w[4];
#pragma unroll
            for (int i = 0; i < 8; i++) a[i] = As[k][ty + 16*i];
#pragma unroll
            for (int j = 0; j < 4; j++) w[j] = Ws[k][tx + 16*j];
#pragma unroll
            for (int i = 0; i < 8; i++)
#pragma unroll
                for (int j = 0; j < 4; j++) acc[i][j] = fmaf(a[i], w[j], acc[i][j]);
        }
        __syncthreads();
    }
#pragma unroll
    for (int i = 0; i < 8; i++) {
        int m = m0 + ty + 16*i;
#pragma unroll
        for (int j = 0; j < 4; j++) {
            int n = n0 + tx + 16*j;
            if (n < N) C[m*N + n] = acc[i][j];
        }
    }
}

// -------- causal depthwise conv (width 4) + SiLU : reads x half of xz --------
__global__ void k_conv(const float* __restrict__ cw, const float* __restrict__ cb) {
    int idx = blockIdx.x * blockDim.x + threadIdx.x;
    if (idx >= ROWS*DI) return;
    int d = idx % DI;
    int r = idx / DI;          // b*L + l
    int l = r % L_SZ;
    float s = cb[d];
#pragma unroll
    for (int j = 0; j < DCV; j++) {
        int t = l - (DCV-1) + j;
        if (t >= 0) s = fmaf(cw[d*DCV + j], g_xz[(r - l + t)*XZW + d], s);
    }
    g_xc[idx] = s / (1.f + __expf(-s));   // silu
}

// -------- dt projection + softplus: dt = softplus(dbc[:, :11] @ dtw^T + dtb) --------
__global__ void k_dtproj(const float* __restrict__ dtw, const float* __restrict__ dtb) {
    int row = blockIdx.x;
    __shared__ float as[DTR];
    int t = threadIdx.x;
    if (t < DTR) as[t] = g_dbc[row*DBCW + t];
    __syncthreads();
    if (t < DI) {
        float acc = dtb[t];
#pragma unroll
        for (int k = 0; k < DTR; k++) acc = fmaf(as[k], dtw[t*DTR + k], acc);
        float sp = (acc > 15.f) ? acc : log1pf(__expf(acc));
        g_dt[row*DI + t] = sp;
    }
}

// -------- selective scan: 16 lanes per (b,d) channel, fused D*x + z-gate --------
__global__ void k_scan(const float* __restrict__ A_log, const float* __restrict__ Dp) {
    int b = blockIdx.x;
    int g = threadIdx.x >> 4;          // channel group within block (8 per block)
    int n = threadIdx.x & 15;          // state index
    int d = blockIdx.y * 8 + g;
    bool valid = (d < DI);
    if (!valid) d = DI - 1;            // clamp for safe (redundant) loads
    float A  = -__expf(A_log[d*DS + n]);
    float Dv = Dp[d];
    float h = 0.f;
    int row = b * L_SZ;
    // prefetch step 0
    float dtv = g_dt[row*DI + d];
    float xv  = g_xc[row*DI + d];
    float Bv  = g_dbc[row*DBCW + DTR + n];
    float Cv  = g_dbc[row*DBCW + DTR + DS + n];
    float zv  = g_xz[row*XZW + DI + d];
    for (int l = 0; l < L_SZ; l++) {
        int nrow = row + 1;
        float dtn = 0.f, xn = 0.f, Bn = 0.f, Cn = 0.f, zn = 0.f;
        if (l + 1 < L_SZ) {            // prefetch next step (hides L2 latency)
            dtn = g_dt[nrow*DI + d];
            xn  = g_xc[nrow*DI + d];
            Bn  = g_dbc[nrow*DBCW + DTR + n];
            Cn  = g_dbc[nrow*DBCW + DTR + DS + n];
            zn  = g_xz[nrow*XZW + DI + d];
        }
        float dA = __expf(dtv * A);
        h = fmaf(dA, h, dtv * xv * Bv);
        float yp = h * Cv;
        yp += __shfl_xor_sync(0xffffffffu, yp, 8);
        yp += __shfl_xor_sync(0xffffffffu, yp, 4);
        yp += __shfl_xor_sync(0xffffffffu, yp, 2);
        yp += __shfl_xor_sync(0xffffffffu, yp, 1);
        if (n == 0 && valid) {
            float sz = zv / (1.f + __expf(-zv));     // silu(z)
            g_y[row*DI + d] = (yp + Dv * xv) * sz;
        }
        row = nrow;
        dtv = dtn; xv = xn; Bv = Bn; Cv = Cn; zv = zn;
    }
}

// ----------------------------------------------------------------------------
extern "C" void kernel_launch(void* const* d_in, const int* in_sizes, int n_in,
                              void* d_out, int out_size) {
    const int*   fasta = (const int*)  d_in[0];
    const float* emb   = (const float*)d_in[1];
    const float* in_w  = (const float*)d_in[2];   // (3, 664, 166)
    const float* cw    = (const float*)d_in[3];   // (3, 332, 4)
    const float* cb    = (const float*)d_in[4];   // (3, 332)
    const float* xw    = (const float*)d_in[5];   // (3, 43, 332)
    const float* dtw   = (const float*)d_in[6];   // (3, 332, 11)
    const float* dtb   = (const float*)d_in[7];   // (3, 332)
    const float* Alog  = (const float*)d_in[8];   // (3, 332, 16)
    const float* Dp    = (const float*)d_in[9];   // (3, 332)
    const float* ow    = (const float*)d_in[10];  // (3, 166, 332)
    const float* nw    = (const float*)d_in[11];  // (3, 166)
    const float* nfw   = (const float*)d_in[12];  // (166)
    float* out = (float*)d_out;                   // [ve (16*166) | v (16*1024*166)]

    float *hn, *xz, *xc, *dbc, *y;
    cudaGetSymbolAddress((void**)&hn,  g_hnorm);
    cudaGetSymbolAddress((void**)&xz,  g_xz);
    cudaGetSymbolAddress((void**)&xc,  g_xc);
    cudaGetSymbolAddress((void**)&dbc, g_dbc);
    cudaGetSymbolAddress((void**)&y,   g_y);
    float* hid;
    cudaGetSymbolAddress((void**)&hid, g_hidden);

    k_embed<<<(ROWS*DM + 255)/256, 256>>>(fasta, emb);

    for (int l = 0; l < NLAY; l++) {
        k_addnorm<<<ROWS/8, 256>>>(nw + l*DM, l == 0);
        // xz = hnorm @ in_w^T   (M=16384, N=664, K=166)
        k_gemm<<<dim3((XZW + GTN - 1)/GTN, ROWS/GTM), 256>>>(hn, in_w + l*XZW*DM, xz, XZW, DM);
        // conv + silu
        k_conv<<<(ROWS*DI + 255)/256, 256>>>(cw + l*DI*DCV, cb + l*DI);
        // dbc = xc @ xw^T       (M=16384, N=43, K=332)
        k_gemm<<<dim3((DBCW + GTN - 1)/GTN, ROWS/GTM), 256>>>(xc, xw + l*DBCW*DI, dbc, DBCW, DI);
        // dt = softplus(dbc[:, :11] @ dtw^T + dtb)
        k_dtproj<<<ROWS, 384>>>(dtw + l*DI*DTR, dtb + l*DI);
        // selective scan (fused D*x + silu(z) gate)
        k_scan<<<dim3(B_SZ, (DI + 7)/8), 128>>>(Alog + l*DI*DS, Dp + l*DI);
        // hidden = y @ ow^T     (M=16384, N=166, K=332)
        k_gemm<<<dim3((DM + GTN - 1)/GTN, ROWS/GTM), 256>>>(y, ow + l*DM*DI, hid, DM, DI);
    }

    k_finalnorm<<<ROWS/8, 256>>>(nfw, out + B_SZ*DM);
    k_maxL<<<(B_SZ*DM)/8, 256>>>(out + B_SZ*DM, out);
}

// round 2
// speedup vs baseline: 1.2218x; 1.2218x over previous
#include <cuda_runtime.h>
#include <math.h>

#define B_SZ  16
#define L_SZ  1024
#define DM    166
#define DI    332
#define DS    16
#define DCV   4
#define DTR   11
#define NLAY  3
#define XZW   (2*DI)        // 664
#define DBCW  (DTR + 2*DS)  // 43
#define ROWS  (B_SZ*L_SZ)   // 16384
#define EPSV  1e-5f

// -------- scratch (device globals; no allocation allowed) --------
__device__ float g_hidden[ROWS*DM];
__device__ float g_resid [ROWS*DM];
__device__ float g_hnorm [ROWS*DM];
__device__ float g_xz    [ROWS*XZW];
__device__ float g_xc    [ROWS*DI];
__device__ float g_dbc   [ROWS*DBCW];
__device__ float g_dt    [ROWS*DI];
__device__ float g_y     [ROWS*DI];

// -------- fast transcendental helpers --------
__device__ __forceinline__ float fex2(float x) {
    float r; asm("ex2.approx.ftz.f32 %0, %1;" : "=f"(r) : "f"(x)); return r;
}
__device__ __forceinline__ float frcp(float x) {
    float r; asm("rcp.approx.ftz.f32 %0, %1;" : "=f"(r) : "f"(x)); return r;
}
#define LOG2E 1.44269504f
__device__ __forceinline__ float fsilu(float s) {
    return s * frcp(1.f + fex2(-LOG2E * s));
}

// -------- embedding lookup --------
__global__ void k_embed(const int* __restrict__ fasta, const float* __restrict__ emb) {
    int idx = blockIdx.x * blockDim.x + threadIdx.x;
    if (idx >= ROWS*DM) return;
    int r = idx / DM, m = idx - r*DM;
    g_hidden[idx] = emb[fasta[r]*DM + m];
}

// -------- residual add + rmsnorm (warp per row) --------
__global__ void k_addnorm(const float* __restrict__ nw, int first) {
    int row  = blockIdx.x * 8 + (threadIdx.x >> 5);
    int lane = threadIdx.x & 31;
    const float* hp = g_hidden + row*DM;
    float* rp = g_resid + row*DM;
    float v[6]; float ss = 0.f;
#pragma unroll
    for (int j = 0; j < 6; j++) {
        int i = lane + 32*j;
        float x = 0.f;
        if (i < DM) {
            x = hp[i];
            if (!first) x += rp[i];
            rp[i] = x;
        }
        v[j] = x; ss += x*x;
    }
#pragma unroll
    for (int o = 16; o; o >>= 1) ss += __shfl_xor_sync(0xffffffffu, ss, o);
    float sc = rsqrtf(ss * (1.f/DM) + EPSV);
    float* op = g_hnorm + row*DM;
#pragma unroll
    for (int j = 0; j < 6; j++) {
        int i = lane + 32*j;
        if (i < DM) op[i] = v[j] * sc * nw[i];
    }
}

// -------- final residual add + rmsnorm -> v --------
__global__ void k_finalnorm(const float* __restrict__ nfw, float* __restrict__ vout) {
    int row  = blockIdx.x * 8 + (threadIdx.x >> 5);
    int lane = threadIdx.x & 31;
    const float* hp = g_hidden + row*DM;
    const float* rp = g_resid  + row*DM;
    float v[6]; float ss = 0.f;
#pragma unroll
    for (int j = 0; j < 6; j++) {
        int i = lane + 32*j;
        float x = 0.f;
        if (i < DM) x = hp[i] + rp[i];
        v[j] = x; ss += x*x;
    }
#pragma unroll
    for (int o = 16; o; o >>= 1) ss += __shfl_xor_sync(0xffffffffu, ss, o);
    float sc = rsqrtf(ss * (1.f/DM) + EPSV);
    float* op = vout + row*DM;
#pragma unroll
    for (int j = 0; j < 6; j++) {
        int i = lane + 32*j;
        if (i < DM) op[i] = v[j] * sc * nfw[i];
    }
}

// -------- max over L (warp per (b,m)) --------
__global__ void k_maxL(const float* __restrict__ v, float* __restrict__ ve) {
    int w    = blockIdx.x * 8 + (threadIdx.x >> 5);
    int lane = threadIdx.x & 31;
    int b = w / DM, m = w - b*DM;
    float mx = -INFINITY;
    for (int l = lane; l < L_SZ; l += 32)
        mx = fmaxf(mx, v[(b*L_SZ + l)*DM + m]);
#pragma unroll
    for (int o = 16; o; o >>= 1) mx = fmaxf(mx, __shfl_xor_sync(0xffffffffu, mx, o));
    if (lane == 0) ve[b*DM + m] = mx;
}

// -------- fp32 GEMM: C[M,N] = A[M,K] * W[N,K]^T --------
// 128(M) x 64(N) block tile, 256 threads, 8x4 microtile (vectorized LDS.128),
// double-buffered smem with register staging, template K for full unroll.
#define GTM 128
#define GTN 64
#define GTK 16
#define APAD 132
#define WPAD 68
template<int K>
__global__ void __launch_bounds__(256, 2) k_gemm_t(const float* __restrict__ A,
                                                   const float* __restrict__ W,
                                                   float* __restrict__ C, int N) {
    constexpr int KT = (K + GTK - 1) / GTK;
    __shared__ float As[2][GTK][APAD];
    __shared__ float Ws[2][GTK][WPAD];
    int tid = threadIdx.x;
    int m0 = blockIdx.y * GTM;
    int n0 = blockIdx.x * GTN;
    int tx = tid & 15, ty = tid >> 4;

    float acc[8][4];
#pragma unroll
    for (int i = 0; i < 8; i++)
#pragma unroll
        for (int j = 0; j < 4; j++) acc[i][j] = 0.f;

    float Ar[8], Wr[4];

    // ---- tile 0 load ----
#pragma unroll
    for (int i = 0; i < 8; i++) {
        int idx = tid + i*256;
        int m = idx >> 4, k = idx & 15;
        Ar[i] = (k < K) ? A[(m0 + m)*K + k] : 0.f;
    }
#pragma unroll
    for (int i = 0; i < 4; i++) {
        int idx = tid + i*256;
        int n = idx >> 4, k = idx & 15;
        Wr[i] = ((n0 + n) < N && k < K) ? W[(n0 + n)*K + k] : 0.f;
    }
#pragma unroll
    for (int i = 0; i < 8; i++) {
        int idx = tid + i*256;
        As[0][idx & 15][idx >> 4] = Ar[i];
    }
#pragma unroll
    for (int i = 0; i < 4; i++) {
        int idx = tid + i*256;
        Ws[0][idx & 15][idx >> 4] = Wr[i];
    }
    __syncthreads();

#pragma unroll 1
    for (int t = 0; t < KT; t++) {
        int buf = t & 1;
        if (t + 1 < KT) {
            int kk = (t + 1) * GTK;
#pragma unroll
            for (int i = 0; i < 8; i++) {
                int idx = tid + i*256;
                int m = idx >> 4, k = idx & 15;
                Ar[i] = (kk + k < K) ? A[(m0 + m)*K + kk + k] : 0.f;
            }
#pragma unroll
            for (int i = 0; i < 4; i++) {
                int idx = tid + i*256;
                int n = idx >> 4, k = idx & 15;
                Wr[i] = ((n0 + n) < N && (kk + k) < K) ? W[(n0 + n)*K + kk + k] : 0.f;
            }
        }
#pragma unroll
        for (int k = 0; k < GTK; k++) {
            float4 a0 = *(const float4*)&As[buf][k][ty*4];
            float4 a1 = *(const float4*)&As[buf][k][ty*4 + 64];
            float4 w  = *(const float4*)&Ws[buf][k][tx*4];
            float am[8] = {a0.x, a0.y, a0.z, a0.w, a1.x, a1.y, a1.z, a1.w};
            float wn[4] = {w.x, w.y, w.z, w.w};
#pragma unroll
            for (int i = 0; i < 8; i++)
#pragma unroll
                for (int j = 0; j < 4; j++)
                    acc[i][j] = fmaf(am[i], wn[j], acc[i][j]);
        }
        if (t + 1 < KT) {
            int nbuf = (t + 1) & 1;
#pragma unroll
            for (int i = 0; i < 8; i++) {
                int idx = tid + i*256;
                As[nbuf][idx & 15][idx >> 4] = Ar[i];
            }
#pragma unroll
            for (int i = 0; i < 4; i++) {
                int idx = tid + i*256;
                Ws[nbuf][idx & 15][idx >> 4] = Wr[i];
            }
        }
        __syncthreads();
    }

#pragma unroll
    for (int i = 0; i < 8; i++) {
        int m = m0 + ty*4 + (i & 3) + (i >> 2)*64;
#pragma unroll
        for (int j = 0; j < 4; j++) {
            int n = n0 + tx*4 + j;
            if (n < N) C[m*N + n] = acc[i][j];
        }
    }
}

// -------- causal depthwise conv (width 4) + SiLU, 4 outputs per thread --------
__global__ void k_conv(const float* __restrict__ cw, const float* __restrict__ cb) {
    int idx = blockIdx.x * blockDim.x + threadIdx.x;   // (ROWS/4)*DI threads
    if (idx >= (ROWS/4)*DI) return;
    int d = idx % DI;
    int q = idx / DI;
    int b = q >> 8;                 // L/4 = 256 quads per batch
    int lq = (q & 255) << 2;
    const float* bp = g_xz + (size_t)b*L_SZ*XZW + d;
    float w0 = cw[d*4+0], w1 = cw[d*4+1], w2 = cw[d*4+2], w3 = cw[d*4+3];
    float bb = cb[d];
    float x[7];
    x[0] = (lq >= 3) ? bp[(lq-3)*XZW] : 0.f;
    x[1] = (lq >= 2) ? bp[(lq-2)*XZW] : 0.f;
    x[2] = (lq >= 1) ? bp[(lq-1)*XZW] : 0.f;
    x[3] = bp[(lq+0)*XZW];
    x[4] = bp[(lq+1)*XZW];
    x[5] = bp[(lq+2)*XZW];
    x[6] = bp[(lq+3)*XZW];
    float* op = g_xc + ((size_t)b*L_SZ + lq)*DI + d;
#pragma unroll
    for (int j = 0; j < 4; j++) {
        float s = bb;
        s = fmaf(w0, x[j],   s);
        s = fmaf(w1, x[j+1], s);
        s = fmaf(w2, x[j+2], s);
        s = fmaf(w3, x[j+3], s);
        op[j*DI] = fsilu(s);
    }
}

// -------- dt projection + softplus (flat, one thread per (row,d)) --------
__global__ void k_dtproj(const float* __restrict__ dtw, const float* __restrict__ dtb) {
    int idx = blockIdx.x * blockDim.x + threadIdx.x;
    if (idx >= ROWS*DI) return;
    int d = idx % DI;
    int row = idx / DI;
    const float* dbcp = g_dbc + row*DBCW;
    float acc = dtb[d];
#pragma unroll
    for (int k = 0; k < DTR; k++) acc = fmaf(dbcp[k], dtw[d*DTR + k], acc);
    g_dt[idx] = (acc > 15.f) ? acc : log1pf(__expf(acc));
}

// -------- selective scan: 16 lanes per (b,d) channel --------
__global__ void k_scan(const float* __restrict__ A_log, const float* __restrict__ Dp) {
    int b = blockIdx.x;
    int g = threadIdx.x >> 4;
    int n = threadIdx.x & 15;
    int d = blockIdx.y * 8 + g;
    bool valid = (d < DI);
    if (!valid) d = DI - 1;
    float A2 = -__expf(A_log[d*DS + n]) * LOG2E;   // pre-fold log2(e)
    float Dv = Dp[d];
    float h = 0.f;
    int row = b * L_SZ;
    float dtv = g_dt[row*DI + d];
    float xv  = g_xc[row*DI + d];
    float Bv  = g_dbc[row*DBCW + DTR + n];
    float Cv  = g_dbc[row*DBCW + DTR + DS + n];
    float zv  = g_xz[row*XZW + DI + d];
    for (int l = 0; l < L_SZ; l++) {
        int nrow = row + 1;
        float dtn = 0.f, xn = 0.f, Bn = 0.f, Cn = 0.f, zn = 0.f;
        if (l + 1 < L_SZ) {
            dtn = g_dt[nrow*DI + d];
            xn  = g_xc[nrow*DI + d];
            Bn  = g_dbc[nrow*DBCW + DTR + n];
            Cn  = g_dbc[nrow*DBCW + DTR + DS + n];
            zn  = g_xz[nrow*XZW + DI + d];
        }
        float dA = fex2(dtv * A2);
        h = fmaf(dA, h, dtv * xv * Bv);
        float yp = h * Cv;
        yp += __shfl_xor_sync(0xffffffffu, yp, 8);
        yp += __shfl_xor_sync(0xffffffffu, yp, 4);
        yp += __shfl_xor_sync(0xffffffffu, yp, 2);
        yp += __shfl_xor_sync(0xffffffffu, yp, 1);
        if (n == 0 && valid) {
            g_y[row*DI + d] = fmaf(Dv, xv, yp) * fsilu(zv);
        }
        row = nrow;
        dtv = dtn; xv = xn; Bv = Bn; Cv = Cn; zv = zn;
    }
}

// ----------------------------------------------------------------------------
extern "C" void kernel_launch(void* const* d_in, const int* in_sizes, int n_in,
                              void* d_out, int out_size) {
    const int*   fasta = (const int*)  d_in[0];
    const float* emb   = (const float*)d_in[1];
    const float* in_w  = (const float*)d_in[2];
    const float* cw    = (const float*)d_in[3];
    const float* cb    = (const float*)d_in[4];
    const float* xw    = (const float*)d_in[5];
    const float* dtw   = (const float*)d_in[6];
    const float* dtb   = (const float*)d_in[7];
    const float* Alog  = (const float*)d_in[8];
    const float* Dp    = (const float*)d_in[9];
    const float* ow    = (const float*)d_in[10];
    const float* nw    = (const float*)d_in[11];
    const float* nfw   = (const float*)d_in[12];
    float* out = (float*)d_out;                   // [ve (16*166) | v (16*1024*166)]

    float *hn, *xz, *xc, *dbc, *y, *hid;
    cudaGetSymbolAddress((void**)&hn,  g_hnorm);
    cudaGetSymbolAddress((void**)&xz,  g_xz);
    cudaGetSymbolAddress((void**)&xc,  g_xc);
    cudaGetSymbolAddress((void**)&dbc, g_dbc);
    cudaGetSymbolAddress((void**)&y,   g_y);
    cudaGetSymbolAddress((void**)&hid, g_hidden);

    k_embed<<<(ROWS*DM + 255)/256, 256>>>(fasta, emb);

    for (int l = 0; l < NLAY; l++) {
        k_addnorm<<<ROWS/8, 256>>>(nw + l*DM, l == 0);
        // xz = hnorm @ in_w^T   (M=16384, N=664, K=166)
        k_gemm_t<DM><<<dim3((XZW + GTN - 1)/GTN, ROWS/GTM), 256>>>(hn, in_w + l*XZW*DM, xz, XZW);
        // conv + silu
        k_conv<<<((ROWS/4)*DI + 255)/256, 256>>>(cw + l*DI*DCV, cb + l*DI);
        // dbc = xc @ xw^T       (M=16384, N=43, K=332)
        k_gemm_t<DI><<<dim3((DBCW + GTN - 1)/GTN, ROWS/GTM), 256>>>(xc, xw + l*DBCW*DI, dbc, DBCW);
        // dt = softplus(dbc[:, :11] @ dtw^T + dtb)
        k_dtproj<<<(ROWS*DI + 255)/256, 256>>>(dtw + l*DI*DTR, dtb + l*DI);
        // selective scan (fused D*x + silu(z) gate)
        k_scan<<<dim3(B_SZ, (DI + 7)/8), 128>>>(Alog + l*DI*DS, Dp + l*DI);
        // hidden = y @ ow^T     (M=16384, N=166, K=332)
        k_gemm_t<DI><<<dim3((DM + GTN - 1)/GTN, ROWS/GTM), 256>>>(y, ow + l*DM*DI, hid, DM);
    }

    k_finalnorm<<<ROWS/8, 256>>>(nfw, out + B_SZ*DM);
    k_maxL<<<(B_SZ*DM)/8, 256>>>(out + B_SZ*DM, out);
}

// round 4
// speedup vs baseline: 1.4480x; 1.1851x over previous
#include <cuda_runtime.h>
#include <cuda_bf16.h>
#include <math.h>
#include <stdint.h>

#define B_SZ  16
#define L_SZ  1024
#define DM    166
#define DI    332
#define DS    16
#define DCV   4
#define DTR   11
#define NLAY  3
#define XZW   (2*DI)        // 664
#define DBCW  (DTR + 2*DS)  // 43
#define ROWS  (B_SZ*L_SZ)   // 16384
#define EPSV  1e-5f

// -------- scratch (device globals; no allocation allowed) --------
__device__ float g_hidden[ROWS*DM];
__device__ float g_resid [ROWS*DM];
__device__ float g_hnorm [ROWS*DM];
__device__ float g_xz    [ROWS*XZW];
__device__ float g_xc    [ROWS*DI];
__device__ float g_dbc   [ROWS*DBCW];
__device__ float g_dt    [ROWS*DI];
__device__ float g_y     [ROWS*DI];

// -------- fast transcendental helpers --------
__device__ __forceinline__ float fex2(float x) {
    float r; asm("ex2.approx.ftz.f32 %0, %1;" : "=f"(r) : "f"(x)); return r;
}
__device__ __forceinline__ float frcp(float x) {
    float r; asm("rcp.approx.ftz.f32 %0, %1;" : "=f"(r) : "f"(x)); return r;
}
#define LOG2E 1.44269504f
__device__ __forceinline__ float fsilu(float s) {
    return s * frcp(1.f + fex2(-LOG2E * s));
}

// ==================== split-bf16 HMMA GEMM ====================
// C[M,N] = A[M,K] * W[N,K]^T via mma.sync.m16n8k16 bf16, 3-MMA hi/lo split.
// Block tile 128(M) x 64(N) x 32(K), 8 warps (4 in M x 2 in N), warp = 32x32.
#define BM 128
#define BN 64
#define BK 32
#define LDK 40   // padded smem row length (bf16 elems) -> conflict-free frags

__device__ __forceinline__ void mma_bf16(float* c, const uint32_t* a, const uint32_t* b) {
    asm volatile(
        "mma.sync.aligned.m16n8k16.row.col.f32.bf16.bf16.f32 "
        "{%0,%1,%2,%3}, {%4,%5,%6,%7}, {%8,%9}, {%0,%1,%2,%3};"
        : "+f"(c[0]), "+f"(c[1]), "+f"(c[2]), "+f"(c[3])
        : "r"(a[0]), "r"(a[1]), "r"(a[2]), "r"(a[3]), "r"(b[0]), "r"(b[1]));
}

template<int K, bool NEVEN>
__global__ void __launch_bounds__(256) k_hgemm(const float* __restrict__ A,
                                               const float* __restrict__ W,
                                               float* __restrict__ C, int N) {
    __shared__ __nv_bfloat16 Ah[BM][LDK];
    __shared__ __nv_bfloat16 Al[BM][LDK];
    __shared__ __nv_bfloat16 Bh[BN][LDK];
    __shared__ __nv_bfloat16 Bl[BN][LDK];

    constexpr int KT = (K + BK - 1) / BK;
    int tid  = threadIdx.x;
    int wid  = tid >> 5;
    int lane = tid & 31;
    int wm = wid & 3;          // M quadrant (32 rows)
    int wn = wid >> 2;         // N half (32 cols)
    int grp = lane >> 2;       // 0..7
    int tig = lane & 3;        // 0..3
    int m0 = blockIdx.y * BM;
    int n0 = blockIdx.x * BN;

    float acc[2][4][4];
#pragma unroll
    for (int i = 0; i < 2; i++)
#pragma unroll
        for (int j = 0; j < 4; j++)
#pragma unroll
            for (int q = 0; q < 4; q++) acc[i][j][q] = 0.f;

#pragma unroll 1
    for (int t = 0; t < KT; t++) {
        int k0 = t * BK;
        // ---- load + split A tile: 128 x 32 (8 float2 per thread) ----
#pragma unroll
        for (int i = 0; i < 8; i++) {
            int idx = tid + i*256;
            int row = idx >> 4, cp = idx & 15;
            int kg = k0 + cp*2;
            float2 v = make_float2(0.f, 0.f);
            if (kg < K) v = *(const float2*)(A + (size_t)(m0 + row)*K + kg);
            __nv_bfloat16 h0 = __float2bfloat16(v.x);
            __nv_bfloat16 h1 = __float2bfloat16(v.y);
            Ah[row][cp*2]   = h0;
            Ah[row][cp*2+1] = h1;
            Al[row][cp*2]   = __float2bfloat16(v.x - __bfloat162float(h0));
            Al[row][cp*2+1] = __float2bfloat16(v.y - __bfloat162float(h1));
        }
        // ---- load + split B tile: 64 x 32 (4 float2 per thread) ----
#pragma unroll
        for (int i = 0; i < 4; i++) {
            int idx = tid + i*256;
            int row = idx >> 4, cp = idx & 15;
            int kg = k0 + cp*2;
            int n = n0 + row;
            float2 v = make_float2(0.f, 0.f);
            if (n < N && kg < K) v = *(const float2*)(W + (size_t)n*K + kg);
            __nv_bfloat16 h0 = __float2bfloat16(v.x);
            __nv_bfloat16 h1 = __float2bfloat16(v.y);
            Bh[row][cp*2]   = h0;
            Bh[row][cp*2+1] = h1;
            Bl[row][cp*2]   = __float2bfloat16(v.x - __bfloat162float(h0));
            Bl[row][cp*2+1] = __float2bfloat16(v.y - __bfloat162float(h1));
        }
        __syncthreads();

        // ---- compute: 2 k-steps of 16, fragments from smem ----
#pragma unroll
        for (int ks = 0; ks < BK; ks += 16) {
            uint32_t ah[2][4], al[2][4], bh[4][2], bl[4][2];
#pragma unroll
            for (int i = 0; i < 2; i++) {
                int r = wm*32 + i*16 + grp;
                ah[i][0] = *(const uint32_t*)&Ah[r  ][ks + tig*2];
                ah[i][1] = *(const uint32_t*)&Ah[r+8][ks + tig*2];
                ah[i][2] = *(const uint32_t*)&Ah[r  ][ks + 8 + tig*2];
                ah[i][3] = *(const uint32_t*)&Ah[r+8][ks + 8 + tig*2];
                al[i][0] = *(const uint32_t*)&Al[r  ][ks + tig*2];
                al[i][1] = *(const uint32_t*)&Al[r+8][ks + tig*2];
                al[i][2] = *(const uint32_t*)&Al[r  ][ks + 8 + tig*2];
                al[i][3] = *(const uint32_t*)&Al[r+8][ks + 8 + tig*2];
            }
#pragma unroll
            for (int j = 0; j < 4; j++) {
                int cn = wn*32 + j*8 + grp;
                bh[j][0] = *(const uint32_t*)&Bh[cn][ks + tig*2];
                bh[j][1] = *(const uint32_t*)&Bh[cn][ks + 8 + tig*2];
                bl[j][0] = *(const uint32_t*)&Bl[cn][ks + tig*2];
                bl[j][1] = *(const uint32_t*)&Bl[cn][ks + 8 + tig*2];
            }
#pragma unroll
            for (int i = 0; i < 2; i++)
#pragma unroll
                for (int j = 0; j < 4; j++) {
                    mma_bf16(acc[i][j], ah[i], bh[j]);   // hi*hi
                    mma_bf16(acc[i][j], ah[i], bl[j]);   // hi*lo
                    mma_bf16(acc[i][j], al[i], bh[j]);   // lo*hi
                }
        }
        __syncthreads();
    }

    // ---- epilogue ----
#pragma unroll
    for (int i = 0; i < 2; i++) {
#pragma unroll
        for (int j = 0; j < 4; j++) {
            int mb = m0 + wm*32 + i*16 + grp;
            int nb = n0 + wn*32 + j*8 + tig*2;
            if (NEVEN) {
                if (nb < N) {
                    *(float2*)(C + (size_t)mb*N + nb)     = make_float2(acc[i][j][0], acc[i][j][1]);
                    *(float2*)(C + (size_t)(mb+8)*N + nb) = make_float2(acc[i][j][2], acc[i][j][3]);
                }
            } else {
                if (nb < N)     { C[(size_t)mb*N + nb]       = acc[i][j][0];
                                  C[(size_t)(mb+8)*N + nb]   = acc[i][j][2]; }
                if (nb + 1 < N) { C[(size_t)mb*N + nb+1]     = acc[i][j][1];
                                  C[(size_t)(mb+8)*N + nb+1] = acc[i][j][3]; }
            }
        }
    }
}

// -------- embedding lookup --------
__global__ void k_embed(const int* __restrict__ fasta, const float* __restrict__ emb) {
    int idx = blockIdx.x * blockDim.x + threadIdx.x;
    if (idx >= ROWS*DM) return;
    int r = idx / DM, m = idx - r*DM;
    g_hidden[idx] = emb[fasta[r]*DM + m];
}

// -------- residual add + rmsnorm (warp per row) --------
__global__ void k_addnorm(const float* __restrict__ nw, int first) {
    int row  = blockIdx.x * 8 + (threadIdx.x >> 5);
    int lane = threadIdx.x & 31;
    const float* hp = g_hidden + row*DM;
    float* rp = g_resid + row*DM;
    float v[6]; float ss = 0.f;
#pragma unroll
    for (int j = 0; j < 6; j++) {
        int i = lane + 32*j;
        float x = 0.f;
        if (i < DM) {
            x = hp[i];
            if (!first) x += rp[i];
            rp[i] = x;
        }
        v[j] = x; ss += x*x;
    }
#pragma unroll
    for (int o = 16; o; o >>= 1) ss += __shfl_xor_sync(0xffffffffu, ss, o);
    float sc = rsqrtf(ss * (1.f/DM) + EPSV);
    float* op = g_hnorm + row*DM;
#pragma unroll
    for (int j = 0; j < 6; j++) {
        int i = lane + 32*j;
        if (i < DM) op[i] = v[j] * sc * nw[i];
    }
}

// -------- final residual add + rmsnorm -> v --------
__global__ void k_finalnorm(const float* __restrict__ nfw, float* __restrict__ vout) {
    int row  = blockIdx.x * 8 + (threadIdx.x >> 5);
    int lane = threadIdx.x & 31;
    const float* hp = g_hidden + row*DM;
    const float* rp = g_resid  + row*DM;
    float v[6]; float ss = 0.f;
#pragma unroll
    for (int j = 0; j < 6; j++) {
        int i = lane + 32*j;
        float x = 0.f;
        if (i < DM) x = hp[i] + rp[i];
        v[j] = x; ss += x*x;
    }
#pragma unroll
    for (int o = 16; o; o >>= 1) ss += __shfl_xor_sync(0xffffffffu, ss, o);
    float sc = rsqrtf(ss * (1.f/DM) + EPSV);
    float* op = vout + row*DM;
#pragma unroll
    for (int j = 0; j < 6; j++) {
        int i = lane + 32*j;
        if (i < DM) op[i] = v[j] * sc * nfw[i];
    }
}

// -------- max over L (warp per (b,m)) --------
__global__ void k_maxL(const float* __restrict__ v, float* __restrict__ ve) {
    int w    = blockIdx.x * 8 + (threadIdx.x >> 5);
    int lane = threadIdx.x & 31;
    int b = w / DM, m = w - b*DM;
    float mx = -INFINITY;
    for (int l = lane; l < L_SZ; l += 32)
        mx = fmaxf(mx, v[(b*L_SZ + l)*DM + m]);
#pragma unroll
    for (int o = 16; o; o >>= 1) mx = fmaxf(mx, __shfl_xor_sync(0xffffffffu, mx, o));
    if (lane == 0) ve[b*DM + m] = mx;
}

// -------- causal depthwise conv (width 4) + SiLU, 4 outputs per thread --------
__global__ void k_conv(const float* __restrict__ cw, const float* __restrict__ cb) {
    int idx = blockIdx.x * blockDim.x + threadIdx.x;
    if (idx >= (ROWS/4)*DI) return;
    int d = idx % DI;
    int q = idx / DI;
    int b = q >> 8;
    int lq = (q & 255) << 2;
    const float* bp = g_xz + (size_t)b*L_SZ*XZW + d;
    float w0 = cw[d*4+0], w1 = cw[d*4+1], w2 = cw[d*4+2], w3 = cw[d*4+3];
    float bb = cb[d];
    float x[7];
    x[0] = (lq >= 3) ? bp[(lq-3)*XZW] : 0.f;
    x[1] = (lq >= 2) ? bp[(lq-2)*XZW] : 0.f;
    x[2] = (lq >= 1) ? bp[(lq-1)*XZW] : 0.f;
    x[3] = bp[(lq+0)*XZW];
    x[4] = bp[(lq+1)*XZW];
    x[5] = bp[(lq+2)*XZW];
    x[6] = bp[(lq+3)*XZW];
    float* op = g_xc + ((size_t)b*L_SZ + lq)*DI + d;
#pragma unroll
    for (int j = 0; j < 4; j++) {
        float s = bb;
        s = fmaf(w0, x[j],   s);
        s = fmaf(w1, x[j+1], s);
        s = fmaf(w2, x[j+2], s);
        s = fmaf(w3, x[j+3], s);
        op[j*DI] = fsilu(s);
    }
}

// -------- dt projection + softplus --------
__global__ void k_dtproj(const float* __restrict__ dtw, const float* __restrict__ dtb) {
    int idx = blockIdx.x * blockDim.x + threadIdx.x;
    if (idx >= ROWS*DI) return;
    int d = idx % DI;
    int row = idx / DI;
    const float* dbcp = g_dbc + row*DBCW;
    float acc = dtb[d];
#pragma unroll
    for (int k = 0; k < DTR; k++) acc = fmaf(dbcp[k], dtw[d*DTR + k], acc);
    g_dt[idx] = (acc > 15.f) ? acc : log1pf(__expf(acc));
}

// -------- selective scan: 16 lanes per (b,d) channel --------
__global__ void k_scan(const float* __restrict__ A_log, const float* __restrict__ Dp) {
    int b = blockIdx.x;
    int g = threadIdx.x >> 4;
    int n = threadIdx.x & 15;
    int d = blockIdx.y * 8 + g;
    bool valid = (d < DI);
    if (!valid) d = DI - 1;
    float A2 = -__expf(A_log[d*DS + n]) * LOG2E;
    float Dv = Dp[d];
    float h = 0.f;
    int row = b * L_SZ;
    float dtv = g_dt[row*DI + d];
    float xv  = g_xc[row*DI + d];
    float Bv  = g_dbc[row*DBCW + DTR + n];
    float Cv  = g_dbc[row*DBCW + DTR + DS + n];
    float zv  = g_xz[row*XZW + DI + d];
    for (int l = 0; l < L_SZ; l++) {
        int nrow = row + 1;
        float dtn = 0.f, xn = 0.f, Bn = 0.f, Cn = 0.f, zn = 0.f;
        if (l + 1 < L_SZ) {
            dtn = g_dt[nrow*DI + d];
            xn  = g_xc[nrow*DI + d];
            Bn  = g_dbc[nrow*DBCW + DTR + n];
            Cn  = g_dbc[nrow*DBCW + DTR + DS + n];
            zn  = g_xz[nrow*XZW + DI + d];
        }
        float dA = fex2(dtv * A2);
        h = fmaf(dA, h, dtv * xv * Bv);
        float yp = h * Cv;
        yp += __shfl_xor_sync(0xffffffffu, yp, 8);
        yp += __shfl_xor_sync(0xffffffffu, yp, 4);
        yp += __shfl_xor_sync(0xffffffffu, yp, 2);
        yp += __shfl_xor_sync(0xffffffffu, yp, 1);
        if (n == 0 && valid) {
            g_y[row*DI + d] = fmaf(Dv, xv, yp) * fsilu(zv);
        }
        row = nrow;
        dtv = dtn; xv = xn; Bv = Bn; Cv = Cn; zv = zn;
    }
}

// ----------------------------------------------------------------------------
extern "C" void kernel_launch(void* const* d_in, const int* in_sizes, int n_in,
                              void* d_out, int out_size) {
    const int*   fasta = (const int*)  d_in[0];
    const float* emb   = (const float*)d_in[1];
    const float* in_w  = (const float*)d_in[2];
    const float* cw    = (const float*)d_in[3];
    const float* cb    = (const float*)d_in[4];
    const float* xw    = (const float*)d_in[5];
    const float* dtw   = (const float*)d_in[6];
    const float* dtb   = (const float*)d_in[7];
    const float* Alog  = (const float*)d_in[8];
    const float* Dp    = (const float*)d_in[9];
    const float* ow    = (const float*)d_in[10];
    const float* nw    = (const float*)d_in[11];
    const float* nfw   = (const float*)d_in[12];
    float* out = (float*)d_out;                   // [ve (16*166) | v (16*1024*166)]

    float *hn, *xz, *xc, *dbc, *y, *hid;
    cudaGetSymbolAddress((void**)&hn,  g_hnorm);
    cudaGetSymbolAddress((void**)&xz,  g_xz);
    cudaGetSymbolAddress((void**)&xc,  g_xc);
    cudaGetSymbolAddress((void**)&dbc, g_dbc);
    cudaGetSymbolAddress((void**)&y,   g_y);
    cudaGetSymbolAddress((void**)&hid, g_hidden);

    k_embed<<<(ROWS*DM + 255)/256, 256>>>(fasta, emb);

    for (int l = 0; l < NLAY; l++) {
        k_addnorm<<<ROWS/8, 256>>>(nw + l*DM, l == 0);
        // xz = hnorm @ in_w^T   (M=16384, N=664, K=166)
        k_hgemm<DM, true><<<dim3((XZW + BN - 1)/BN, ROWS/BM), 256>>>(hn, in_w + l*XZW*DM, xz, XZW);
        // conv + silu
        k_conv<<<((ROWS/4)*DI + 255)/256, 256>>>(cw + l*DI*DCV, cb + l*DI);
        // dbc = xc @ xw^T       (M=16384, N=43, K=332)
        k_hgemm<DI, false><<<dim3(1, ROWS/BM), 256>>>(xc, xw + l*DBCW*DI, dbc, DBCW);
        // dt = softplus(dbc[:, :11] @ dtw^T + dtb)
        k_dtproj<<<(ROWS*DI + 255)/256, 256>>>(dtw + l*DI*DTR, dtb + l*DI);
        // selective scan
        k_scan<<<dim3(B_SZ, (DI + 7)/8), 128>>>(Alog + l*DI*DS, Dp + l*DI);
        // hidden = y @ ow^T     (M=16384, N=166, K=332)
        k_hgemm<DI, true><<<dim3((DM + BN - 1)/BN, ROWS/BM), 256>>>(y, ow + l*DM*DI, hid, DM);
    }

    k_finalnorm<<<ROWS/8, 256>>>(nfw, out + B_SZ*DM);
    k_maxL<<<(B_SZ*DM)/8, 256>>>(out + B_SZ*DM, out);
}

// round 5
// speedup vs baseline: 2.1131x; 1.4593x over previous
#include <cuda_runtime.h>
#include <cuda_bf16.h>
#include <math.h>
#include <stdint.h>

#define B_SZ  16
#define L_SZ  1024
#define DM    166
#define DI    332
#define DS    16
#define DCV   4
#define DTR   11
#define NLAY  3
#define XZW   (2*DI)        // 664
#define DBCW  (DTR + 2*DS)  // 43
#define ROWS  (B_SZ*L_SZ)   // 16384
#define EPSV  1e-5f
#define SEG   16
#define SLEN  (L_SZ/SEG)    // 64

// -------- scratch (device globals; no allocation allowed) --------
__device__ float g_hidden[ROWS*DM];
__device__ float g_resid [ROWS*DM];
__device__ float g_hnorm [ROWS*DM];
__device__ float g_xz    [ROWS*XZW];
__device__ float g_xc    [ROWS*DI];
__device__ float g_dbc   [ROWS*DBCW];
__device__ float g_dt    [ROWS*DI];
__device__ float g_y     [ROWS*DI];
__device__ float g_segP  [B_SZ*DI*SEG*DS];
__device__ float g_segH  [B_SZ*DI*SEG*DS];
__device__ float g_segS  [B_SZ*DI*SEG*DS];

// -------- fast transcendental helpers --------
__device__ __forceinline__ float fex2(float x) {
    float r; asm("ex2.approx.ftz.f32 %0, %1;" : "=f"(r) : "f"(x)); return r;
}
__device__ __forceinline__ float frcp(float x) {
    float r; asm("rcp.approx.ftz.f32 %0, %1;" : "=f"(r) : "f"(x)); return r;
}
#define LOG2E 1.44269504f
__device__ __forceinline__ float fsilu(float s) {
    return s * frcp(1.f + fex2(-LOG2E * s));
}

// ==================== split-bf16 HMMA GEMM (pipelined) ====================
#define BM 128
#define BN 64
#define BK 32
#define LDK 40   // padded smem row (bf16) -> conflict-free fragment loads

__device__ __forceinline__ void mma_bf16(float* c, const uint32_t* a, const uint32_t* b) {
    asm volatile(
        "mma.sync.aligned.m16n8k16.row.col.f32.bf16.bf16.f32 "
        "{%0,%1,%2,%3}, {%4,%5,%6,%7}, {%8,%9}, {%0,%1,%2,%3};"
        : "+f"(c[0]), "+f"(c[1]), "+f"(c[2]), "+f"(c[3])
        : "r"(a[0]), "r"(a[1]), "r"(a[2]), "r"(a[3]), "r"(b[0]), "r"(b[1]));
}

template<int K, bool NEVEN>
__global__ void __launch_bounds__(256) k_hgemm(const float* __restrict__ A,
                                               const float* __restrict__ W,
                                               float* __restrict__ C, int N) {
    __shared__ __nv_bfloat16 Ah[BM][LDK];
    __shared__ __nv_bfloat16 Al[BM][LDK];
    __shared__ __nv_bfloat16 Bh[BN][LDK];
    __shared__ __nv_bfloat16 Bl[BN][LDK];

    constexpr int KT = (K + BK - 1) / BK;
    int tid  = threadIdx.x;
    int wid  = tid >> 5;
    int lane = tid & 31;
    int wm = wid & 3;
    int wn = wid >> 2;
    int grp = lane >> 2;
    int tig = lane & 3;
    int m0 = blockIdx.y * BM;
    int n0 = blockIdx.x * BN;

    int arow = tid >> 4, acp = tid & 15;       // A: each thread owns 8 (row+i*16, col acp)
    int brow = tid >> 4, bcp = tid & 15;       // B: 4 rows

    float acc[2][4][4];
#pragma unroll
    for (int i = 0; i < 2; i++)
#pragma unroll
        for (int j = 0; j < 4; j++)
#pragma unroll
            for (int q = 0; q < 4; q++) acc[i][j][q] = 0.f;

    float2 ra[8], rb[4];

    // ---- prologue: load tile 0 into regs ----
#pragma unroll
    for (int i = 0; i < 8; i++) {
        int row = arow + i*16;
        int kg = acp*2;
        ra[i] = (kg < K) ? *(const float2*)(A + (size_t)(m0 + row)*K + kg)
                         : make_float2(0.f, 0.f);
    }
#pragma unroll
    for (int i = 0; i < 4; i++) {
        int row = brow + i*16;
        int kg = bcp*2;
        int n = n0 + row;
        rb[i] = (n < N && kg < K) ? *(const float2*)(W + (size_t)n*K + kg)
                                  : make_float2(0.f, 0.f);
    }

#pragma unroll 1
    for (int t = 0; t < KT; t++) {
        // ---- split + store staged regs to smem ----
#pragma unroll
        for (int i = 0; i < 8; i++) {
            int row = arow + i*16;
            __nv_bfloat16 h0 = __float2bfloat16(ra[i].x);
            __nv_bfloat16 h1 = __float2bfloat16(ra[i].y);
            Ah[row][acp*2]   = h0;
            Ah[row][acp*2+1] = h1;
            Al[row][acp*2]   = __float2bfloat16(ra[i].x - __bfloat162float(h0));
            Al[row][acp*2+1] = __float2bfloat16(ra[i].y - __bfloat162float(h1));
        }
#pragma unroll
        for (int i = 0; i < 4; i++) {
            int row = brow + i*16;
            __nv_bfloat16 h0 = __float2bfloat16(rb[i].x);
            __nv_bfloat16 h1 = __float2bfloat16(rb[i].y);
            Bh[row][bcp*2]   = h0;
            Bh[row][bcp*2+1] = h1;
            Bl[row][bcp*2]   = __float2bfloat16(rb[i].x - __bfloat162float(h0));
            Bl[row][bcp*2+1] = __float2bfloat16(rb[i].y - __bfloat162float(h1));
        }
        __syncthreads();

        // ---- issue next tile's LDGs (latency overlapped with MMA below) ----
        if (t + 1 < KT) {
            int k0 = (t + 1) * BK;
#pragma unroll
            for (int i = 0; i < 8; i++) {
                int row = arow + i*16;
                int kg = k0 + acp*2;
                ra[i] = (kg < K) ? *(const float2*)(A + (size_t)(m0 + row)*K + kg)
                                 : make_float2(0.f, 0.f);
            }
#pragma unroll
            for (int i = 0; i < 4; i++) {
                int row = brow + i*16;
                int kg = k0 + bcp*2;
                int n = n0 + row;
                rb[i] = (n < N && kg < K) ? *(const float2*)(W + (size_t)n*K + kg)
                                          : make_float2(0.f, 0.f);
            }
        }

        // ---- compute from smem ----
#pragma unroll
        for (int ks = 0; ks < BK; ks += 16) {
            uint32_t ah[2][4], al[2][4], bh[4][2], bl[4][2];
#pragma unroll
            for (int i = 0; i < 2; i++) {
                int r = wm*32 + i*16 + grp;
                ah[i][0] = *(const uint32_t*)&Ah[r  ][ks + tig*2];
                ah[i][1] = *(const uint32_t*)&Ah[r+8][ks + tig*2];
                ah[i][2] = *(const uint32_t*)&Ah[r  ][ks + 8 + tig*2];
                ah[i][3] = *(const uint32_t*)&Ah[r+8][ks + 8 + tig*2];
                al[i][0] = *(const uint32_t*)&Al[r  ][ks + tig*2];
                al[i][1] = *(const uint32_t*)&Al[r+8][ks + tig*2];
                al[i][2] = *(const uint32_t*)&Al[r  ][ks + 8 + tig*2];
                al[i][3] = *(const uint32_t*)&Al[r+8][ks + 8 + tig*2];
            }
#pragma unroll
            for (int j = 0; j < 4; j++) {
                int cn = wn*32 + j*8 + grp;
                bh[j][0] = *(const uint32_t*)&Bh[cn][ks + tig*2];
                bh[j][1] = *(const uint32_t*)&Bh[cn][ks + 8 + tig*2];
                bl[j][0] = *(const uint32_t*)&Bl[cn][ks + tig*2];
                bl[j][1] = *(const uint32_t*)&Bl[cn][ks + 8 + tig*2];
            }
#pragma unroll
            for (int i = 0; i < 2; i++)
#pragma unroll
                for (int j = 0; j < 4; j++) {
                    mma_bf16(acc[i][j], ah[i], bh[j]);
                    mma_bf16(acc[i][j], ah[i], bl[j]);
                    mma_bf16(acc[i][j], al[i], bh[j]);
                }
        }
        __syncthreads();
    }

    // ---- epilogue ----
#pragma unroll
    for (int i = 0; i < 2; i++) {
#pragma unroll
        for (int j = 0; j < 4; j++) {
            int mb = m0 + wm*32 + i*16 + grp;
            int nb = n0 + wn*32 + j*8 + tig*2;
            if (NEVEN) {
                if (nb < N) {
                    *(float2*)(C + (size_t)mb*N + nb)     = make_float2(acc[i][j][0], acc[i][j][1]);
                    *(float2*)(C + (size_t)(mb+8)*N + nb) = make_float2(acc[i][j][2], acc[i][j][3]);
                }
            } else {
                if (nb < N)     { C[(size_t)mb*N + nb]       = acc[i][j][0];
                                  C[(size_t)(mb+8)*N + nb]   = acc[i][j][2]; }
                if (nb + 1 < N) { C[(size_t)mb*N + nb+1]     = acc[i][j][1];
                                  C[(size_t)(mb+8)*N + nb+1] = acc[i][j][3]; }
            }
        }
    }
}

// -------- embedding lookup --------
__global__ void k_embed(const int* __restrict__ fasta, const float* __restrict__ emb) {
    int idx = blockIdx.x * blockDim.x + threadIdx.x;
    if (idx >= ROWS*DM) return;
    int r = idx / DM, m = idx - r*DM;
    g_hidden[idx] = emb[fasta[r]*DM + m];
}

// -------- residual add + rmsnorm --------
__global__ void k_addnorm(const float* __restrict__ nw, int first) {
    int row  = blockIdx.x * 8 + (threadIdx.x >> 5);
    int lane = threadIdx.x & 31;
    const float* hp = g_hidden + row*DM;
    float* rp = g_resid + row*DM;
    float v[6]; float ss = 0.f;
#pragma unroll
    for (int j = 0; j < 6; j++) {
        int i = lane + 32*j;
        float x = 0.f;
        if (i < DM) {
            x = hp[i];
            if (!first) x += rp[i];
            rp[i] = x;
        }
        v[j] = x; ss += x*x;
    }
#pragma unroll
    for (int o = 16; o; o >>= 1) ss += __shfl_xor_sync(0xffffffffu, ss, o);
    float sc = rsqrtf(ss * (1.f/DM) + EPSV);
    float* op = g_hnorm + row*DM;
#pragma unroll
    for (int j = 0; j < 6; j++) {
        int i = lane + 32*j;
        if (i < DM) op[i] = v[j] * sc * nw[i];
    }
}

// -------- final residual add + rmsnorm -> v --------
__global__ void k_finalnorm(const float* __restrict__ nfw, float* __restrict__ vout) {
    int row  = blockIdx.x * 8 + (threadIdx.x >> 5);
    int lane = threadIdx.x & 31;
    const float* hp = g_hidden + row*DM;
    const float* rp = g_resid  + row*DM;
    float v[6]; float ss = 0.f;
#pragma unroll
    for (int j = 0; j < 6; j++) {
        int i = lane + 32*j;
        float x = 0.f;
        if (i < DM) x = hp[i] + rp[i];
        v[j] = x; ss += x*x;
    }
#pragma unroll
    for (int o = 16; o; o >>= 1) ss += __shfl_xor_sync(0xffffffffu, ss, o);
    float sc = rsqrtf(ss * (1.f/DM) + EPSV);
    float* op = vout + row*DM;
#pragma unroll
    for (int j = 0; j < 6; j++) {
        int i = lane + 32*j;
        if (i < DM) op[i] = v[j] * sc * nfw[i];
    }
}

// -------- max over L --------
__global__ void k_maxL(const float* __restrict__ v, float* __restrict__ ve) {
    int w    = blockIdx.x * 8 + (threadIdx.x >> 5);
    int lane = threadIdx.x & 31;
    int b = w / DM, m = w - b*DM;
    float mx = -INFINITY;
    for (int l = lane; l < L_SZ; l += 32)
        mx = fmaxf(mx, v[(b*L_SZ + l)*DM + m]);
#pragma unroll
    for (int o = 16; o; o >>= 1) mx = fmaxf(mx, __shfl_xor_sync(0xffffffffu, mx, o));
    if (lane == 0) ve[b*DM + m] = mx;
}

// -------- causal depthwise conv (width 4) + SiLU --------
__global__ void k_conv(const float* __restrict__ cw, const float* __restrict__ cb) {
    int idx = blockIdx.x * blockDim.x + threadIdx.x;
    if (idx >= (ROWS/4)*DI) return;
    int d = idx % DI;
    int q = idx / DI;
    int b = q >> 8;
    int lq = (q & 255) << 2;
    const float* bp = g_xz + (size_t)b*L_SZ*XZW + d;
    float w0 = cw[d*4+0], w1 = cw[d*4+1], w2 = cw[d*4+2], w3 = cw[d*4+3];
    float bb = cb[d];
    float x[7];
    x[0] = (lq >= 3) ? bp[(lq-3)*XZW] : 0.f;
    x[1] = (lq >= 2) ? bp[(lq-2)*XZW] : 0.f;
    x[2] = (lq >= 1) ? bp[(lq-1)*XZW] : 0.f;
    x[3] = bp[(lq+0)*XZW];
    x[4] = bp[(lq+1)*XZW];
    x[5] = bp[(lq+2)*XZW];
    x[6] = bp[(lq+3)*XZW];
    float* op = g_xc + ((size_t)b*L_SZ + lq)*DI + d;
#pragma unroll
    for (int j = 0; j < 4; j++) {
        float s = bb;
        s = fmaf(w0, x[j],   s);
        s = fmaf(w1, x[j+1], s);
        s = fmaf(w2, x[j+2], s);
        s = fmaf(w3, x[j+3], s);
        op[j*DI] = fsilu(s);
    }
}

// -------- dt projection + softplus --------
__global__ void k_dtproj(const float* __restrict__ dtw, const float* __restrict__ dtb) {
    int idx = blockIdx.x * blockDim.x + threadIdx.x;
    if (idx >= ROWS*DI) return;
    int d = idx % DI;
    int row = idx / DI;
    const float* dbcp = g_dbc + row*DBCW;
    float acc = dtb[d];
#pragma unroll
    for (int k = 0; k < DTR; k++) acc = fmaf(dbcp[k], dtw[d*DTR + k], acc);
    g_dt[idx] = (acc > 15.f) ? acc : log1pf(__expf(acc));
}

// -------- chunked scan pass 1: per-segment (prodA, h from 0) --------
__global__ void k_scan1(const float* __restrict__ A_log) {
    int b = blockIdx.x;
    int s = blockIdx.z;
    int g = threadIdx.x >> 4;
    int n = threadIdx.x & 15;
    int d = blockIdx.y * 8 + g;
    bool valid = (d < DI);
    if (!valid) d = DI - 1;
    float A2 = -__expf(A_log[d*DS + n]) * LOG2E;
    float h = 0.f, P = 1.f;
    int row = b*L_SZ + s*SLEN;
#pragma unroll 4
    for (int l = 0; l < SLEN; l++) {
        float dtv = g_dt[row*DI + d];
        float xv  = g_xc[row*DI + d];
        float Bv  = g_dbc[row*DBCW + DTR + n];
        float dA = fex2(dtv * A2);
        h = fmaf(dA, h, dtv * xv * Bv);
        P *= dA;
        row++;
    }
    if (valid) {
        int idx = ((b*DI + d)*SEG + s)*DS + n;
        g_segP[idx] = P;
        g_segH[idx] = h;
    }
}

// -------- chunked scan pass 2: combine segment states --------
__global__ void k_scan2() {
    int idx = blockIdx.x * blockDim.x + threadIdx.x;
    if (idx >= B_SZ*DI*DS) return;
    int n = idx % DS;
    int bd = idx / DS;
    int base = bd*SEG*DS + n;
    float h = 0.f;
#pragma unroll
    for (int s = 0; s < SEG; s++) {
        g_segS[base + s*DS] = h;
        h = fmaf(g_segP[base + s*DS], h, g_segH[base + s*DS]);
    }
}

// -------- chunked scan pass 3: replay with y output --------
__global__ void k_scan3(const float* __restrict__ A_log, const float* __restrict__ Dp) {
    int b = blockIdx.x;
    int s = blockIdx.z;
    int g = threadIdx.x >> 4;
    int n = threadIdx.x & 15;
    int d = blockIdx.y * 8 + g;
    bool valid = (d < DI);
    if (!valid) d = DI - 1;
    float A2 = -__expf(A_log[d*DS + n]) * LOG2E;
    float Dv = Dp[d];
    float h = g_segS[((b*DI + d)*SEG + s)*DS + n];
    int row = b*L_SZ + s*SLEN;
    float dtv = g_dt[row*DI + d];
    float xv  = g_xc[row*DI + d];
    float Bv  = g_dbc[row*DBCW + DTR + n];
    float Cv  = g_dbc[row*DBCW + DTR + DS + n];
    float zv  = g_xz[row*XZW + DI + d];
#pragma unroll 4
    for (int l = 0; l < SLEN; l++) {
        int nrow = row + 1;
        float dtn = 0.f, xn = 0.f, Bn = 0.f, Cn = 0.f, zn = 0.f;
        if (l + 1 < SLEN) {
            dtn = g_dt[nrow*DI + d];
            xn  = g_xc[nrow*DI + d];
            Bn  = g_dbc[nrow*DBCW + DTR + n];
            Cn  = g_dbc[nrow*DBCW + DTR + DS + n];
            zn  = g_xz[nrow*XZW + DI + d];
        }
        float dA = fex2(dtv * A2);
        h = fmaf(dA, h, dtv * xv * Bv);
        float yp = h * Cv;
        yp += __shfl_xor_sync(0xffffffffu, yp, 8);
        yp += __shfl_xor_sync(0xffffffffu, yp, 4);
        yp += __shfl_xor_sync(0xffffffffu, yp, 2);
        yp += __shfl_xor_sync(0xffffffffu, yp, 1);
        if (n == 0 && valid) {
            g_y[row*DI + d] = fmaf(Dv, xv, yp) * fsilu(zv);
        }
        row = nrow;
        dtv = dtn; xv = xn; Bv = Bn; Cv = Cn; zv = zn;
    }
}

// ----------------------------------------------------------------------------
extern "C" void kernel_launch(void* const* d_in, const int* in_sizes, int n_in,
                              void* d_out, int out_size) {
    const int*   fasta = (const int*)  d_in[0];
    const float* emb   = (const float*)d_in[1];
    const float* in_w  = (const float*)d_in[2];
    const float* cw    = (const float*)d_in[3];
    const float* cb    = (const float*)d_in[4];
    const float* xw    = (const float*)d_in[5];
    const float* dtw   = (const float*)d_in[6];
    const float* dtb   = (const float*)d_in[7];
    const float* Alog  = (const float*)d_in[8];
    const float* Dp    = (const float*)d_in[9];
    const float* ow    = (const float*)d_in[10];
    const float* nw    = (const float*)d_in[11];
    const float* nfw   = (const float*)d_in[12];
    float* out = (float*)d_out;                   // [ve (16*166) | v (16*1024*166)]

    float *hn, *xz, *xc, *dbc, *y, *hid;
    cudaGetSymbolAddress((void**)&hn,  g_hnorm);
    cudaGetSymbolAddress((void**)&xz,  g_xz);
    cudaGetSymbolAddress((void**)&xc,  g_xc);
    cudaGetSymbolAddress((void**)&dbc, g_dbc);
    cudaGetSymbolAddress((void**)&y,   g_y);
    cudaGetSymbolAddress((void**)&hid, g_hidden);

    k_embed<<<(ROWS*DM + 255)/256, 256>>>(fasta, emb);

    for (int l = 0; l < NLAY; l++) {
        k_addnorm<<<ROWS/8, 256>>>(nw + l*DM, l == 0);
        // xz = hnorm @ in_w^T   (M=16384, N=664, K=166)
        k_hgemm<DM, true><<<dim3((XZW + BN - 1)/BN, ROWS/BM), 256>>>(hn, in_w + l*XZW*DM, xz, XZW);
        // conv + silu
        k_conv<<<((ROWS/4)*DI + 255)/256, 256>>>(cw + l*DI*DCV, cb + l*DI);
        // dbc = xc @ xw^T       (M=16384, N=43, K=332)
        k_hgemm<DI, false><<<dim3(1, ROWS/BM), 256>>>(xc, xw + l*DBCW*DI, dbc, DBCW);
        // dt = softplus(dbc[:, :11] @ dtw^T + dtb)
        k_dtproj<<<(ROWS*DI + 255)/256, 256>>>(dtw + l*DI*DTR, dtb + l*DI);
        // chunked selective scan
        k_scan1<<<dim3(B_SZ, (DI + 7)/8, SEG), 128>>>(Alog + l*DI*DS);
        k_scan2<<<(B_SZ*DI*DS + 255)/256, 256>>>();
        k_scan3<<<dim3(B_SZ, (DI + 7)/8, SEG), 128>>>(Alog + l*DI*DS, Dp + l*DI);
        // hidden = y @ ow^T     (M=16384, N=166, K=332)
        k_hgemm<DI, true><<<dim3((DM + BN - 1)/BN, ROWS/BM), 256>>>(y, ow + l*DM*DI, hid, DM);
    }

    k_finalnorm<<<ROWS/8, 256>>>(nfw, out + B_SZ*DM);
    k_maxL<<<(B_SZ*DM)/8, 256>>>(out + B_SZ*DM, out);
}